// round 3
// baseline (speedup 1.0000x reference)
#include <cuda_runtime.h>
#include <math.h>

// Problem constants
#define M_ROWS   16384   // B*H*W = 16*32*32
#define N_CODES  8192
#define DIM      512

// GEMM tiling
#define BM 64
#define BN 128
#define BK 16
#define TXN 16   // threads along codes
#define TYN 16   // threads along rows
// 256 threads, each computes 4 rows x 8 cols

// -------- device scratch (no allocations allowed) --------
__device__ float g_cnorm[N_CODES];
__device__ int   g_idx[M_ROWS];
__device__ float g_rowloss[M_ROWS];
__device__ int   g_counts[N_CODES];

// -------- packed fp32x2 helpers (Blackwell FFMA2 path) --------
__device__ __forceinline__ unsigned long long pack2(float x) {
    unsigned long long r;
    asm("mov.b64 %0, {%1, %1};" : "=l"(r) : "f"(x));
    return r;
}
__device__ __forceinline__ void fma2(unsigned long long &d,
                                     unsigned long long a,
                                     unsigned long long b) {
    asm("fma.rn.f32x2 %0, %1, %2, %0;" : "+l"(d) : "l"(a), "l"(b));
}
__device__ __forceinline__ void unpack2(float &lo, float &hi, unsigned long long v) {
    asm("mov.b64 {%0, %1}, %2;" : "=f"(lo), "=f"(hi) : "l"(v));
}

// ============================================================
// Kernel A: codebook row norms |c_j|^2, also zero the histogram
// ============================================================
__global__ void cnorm_kernel(const float* __restrict__ cb) {
    int code = blockIdx.x;                 // 8192 blocks, 128 threads
    int t = threadIdx.x;
    const float4* row = reinterpret_cast<const float4*>(cb + (size_t)code * DIM);
    float4 v = row[t];                     // 512 floats = 128 float4
    float s = v.x*v.x + v.y*v.y + v.z*v.z + v.w*v.w;
    #pragma unroll
    for (int o = 16; o > 0; o >>= 1) s += __shfl_down_sync(0xffffffffu, s, o);
    __shared__ float ws[4];
    if ((t & 31) == 0) ws[t >> 5] = s;
    __syncthreads();
    if (t == 0) {
        g_cnorm[code] = ws[0] + ws[1] + ws[2] + ws[3];
        g_counts[code] = 0;
    }
}

// ============================================================
// Kernel B: fused fp32 GEMM (X @ C^T) + per-row argmin of
//           d'_j = |c_j|^2 - 2 * x.c_j   (|x|^2 dropped: argmin-invariant)
// ============================================================
__global__ __launch_bounds__(256) void dist_argmin_kernel(
    const float* __restrict__ X,
    const float* __restrict__ C,
    float* __restrict__ idx_out)
{
    __shared__ __align__(16) float As[BK][BM];   // 4 KB, [k][m]
    __shared__ __align__(16) float Bs[BK][BN];   // 8 KB, [k][n]
    __shared__ float Cn[BN];
    __shared__ float RedD[TXN][BM];              // 4 KB
    __shared__ int   RedJ[TXN][BM];              // 4 KB

    const int tid = threadIdx.x;
    const int tx = tid & 15;       // code group
    const int ty = tid >> 4;       // row group
    const int row0_blk = blockIdx.x * BM;

    // gmem load mapping
    const int ar  = tid >> 2;      // 0..63 : A row within tile
    const int ac4 = tid & 3;       // 0..3  : A float4 within 16-col chunk
    const int br  = tid & 127;     // 0..127: B code within tile
    const int bc4 = tid >> 7;      // 0..1

    float bestd[4];
    int   bestj[4];
    #pragma unroll
    for (int i = 0; i < 4; i++) { bestd[i] = 3.4e38f; bestj[i] = 0; }

    const float* Abase = X + (size_t)(row0_blk + ar) * DIM + ac4 * 4;

    for (int nt = 0; nt < N_CODES / BN; nt++) {
        const int col0 = nt * BN;
        __syncthreads();                       // protect Cn vs previous epilogue
        if (tid < BN) Cn[tid] = g_cnorm[col0 + tid];

        unsigned long long acc[4][4];
        #pragma unroll
        for (int i = 0; i < 4; i++)
            #pragma unroll
            for (int p = 0; p < 4; p++) acc[i][p] = 0ull;

        for (int kt = 0; kt < DIM / BK; kt++) {
            // ---- load A chunk: 64x16 ----
            float4 av = *reinterpret_cast<const float4*>(Abase + kt * BK);
            As[ac4*4 + 0][ar] = av.x;
            As[ac4*4 + 1][ar] = av.y;
            As[ac4*4 + 2][ar] = av.z;
            As[ac4*4 + 3][ar] = av.w;
            // ---- load B chunk: 128x16 ----
            const float* Bbase = C + (size_t)(col0 + br) * DIM + kt * BK;
            #pragma unroll
            for (int q = 0; q < 2; q++) {
                int f4 = bc4 + q * 2;          // 0..3
                float4 bv = *reinterpret_cast<const float4*>(Bbase + f4 * 4);
                Bs[f4*4 + 0][br] = bv.x;
                Bs[f4*4 + 1][br] = bv.y;
                Bs[f4*4 + 2][br] = bv.z;
                Bs[f4*4 + 3][br] = bv.w;
            }
            __syncthreads();

            #pragma unroll
            for (int k = 0; k < BK; k++) {
                float4 a4 = *reinterpret_cast<const float4*>(&As[k][ty * 4]);
                unsigned long long a0 = pack2(a4.x);
                unsigned long long a1 = pack2(a4.y);
                unsigned long long a2 = pack2(a4.z);
                unsigned long long a3 = pack2(a4.w);
                const ulonglong2* bp =
                    reinterpret_cast<const ulonglong2*>(&Bs[k][tx * 8]);
                ulonglong2 bA = bp[0];
                ulonglong2 bB = bp[1];
                fma2(acc[0][0], a0, bA.x); fma2(acc[0][1], a0, bA.y);
                fma2(acc[0][2], a0, bB.x); fma2(acc[0][3], a0, bB.y);
                fma2(acc[1][0], a1, bA.x); fma2(acc[1][1], a1, bA.y);
                fma2(acc[1][2], a1, bB.x); fma2(acc[1][3], a1, bB.y);
                fma2(acc[2][0], a2, bA.x); fma2(acc[2][1], a2, bA.y);
                fma2(acc[2][2], a2, bB.x); fma2(acc[2][3], a2, bB.y);
                fma2(acc[3][0], a3, bA.x); fma2(acc[3][1], a3, bA.y);
                fma2(acc[3][2], a3, bB.x); fma2(acc[3][3], a3, bB.y);
            }
            __syncthreads();
        }

        // ---- epilogue: running argmin over this code tile ----
        #pragma unroll
        for (int i = 0; i < 4; i++) {
            #pragma unroll
            for (int p = 0; p < 4; p++) {
                float lo, hi;
                unpack2(lo, hi, acc[i][p]);
                int cc = tx * 8 + p * 2;
                float d0 = Cn[cc]     - 2.0f * lo;
                float d1 = Cn[cc + 1] - 2.0f * hi;
                int j0 = col0 + cc;
                if (d0 < bestd[i]) { bestd[i] = d0; bestj[i] = j0; }
                if (d1 < bestd[i]) { bestd[i] = d1; bestj[i] = j0 + 1; }
            }
        }
    }

    // ---- cross-thread argmin reduction (16 tx threads per row) ----
    __syncthreads();
    #pragma unroll
    for (int i = 0; i < 4; i++) {
        RedD[tx][ty * 4 + i] = bestd[i];
        RedJ[tx][ty * 4 + i] = bestj[i];
    }
    __syncthreads();
    if (tid < BM) {
        int r = tid;
        float bd = RedD[0][r];
        int   bj = RedJ[0][r];
        #pragma unroll
        for (int t2 = 1; t2 < TXN; t2++) {
            float d = RedD[t2][r];
            int   j = RedJ[t2][r];
            if (d < bd || (d == bd && j < bj)) { bd = d; bj = j; }
        }
        int grow = row0_blk + r;
        g_idx[grow] = bj;
        idx_out[grow] = (float)bj;          // indices emitted as fp32
    }
}

// ============================================================
// Kernel C: gather z_q, compute z_q_st = z_e + (z_q - z_e),
//           per-row sum of (z_q - z_e)^2, histogram counts
// ============================================================
__global__ void gather_kernel(const float* __restrict__ X,
                              const float* __restrict__ C,
                              float* __restrict__ out_zq)
{
    int row = blockIdx.x;              // 16384 blocks, 128 threads
    int t = threadIdx.x;
    int j = g_idx[row];
    const float4* xr = reinterpret_cast<const float4*>(X + (size_t)row * DIM);
    const float4* cr = reinterpret_cast<const float4*>(C + (size_t)j * DIM);
    float4 x = xr[t];
    float4 c = cr[t];
    float4 d;
    d.x = c.x - x.x; d.y = c.y - x.y; d.z = c.z - x.z; d.w = c.w - x.w;
    float4 o;
    o.x = x.x + d.x; o.y = x.y + d.y; o.z = x.z + d.z; o.w = x.w + d.w;
    reinterpret_cast<float4*>(out_zq + (size_t)row * DIM)[t] = o;

    float s = d.x*d.x + d.y*d.y + d.z*d.z + d.w*d.w;
    #pragma unroll
    for (int o2 = 16; o2 > 0; o2 >>= 1) s += __shfl_down_sync(0xffffffffu, s, o2);
    __shared__ float ws[4];
    if ((t & 31) == 0) ws[t >> 5] = s;
    __syncthreads();
    if (t == 0) {
        g_rowloss[row] = ws[0] + ws[1] + ws[2] + ws[3];
        atomicAdd(&g_counts[j], 1);
    }
}

// ============================================================
// Kernel D: losses + perplexity (single block, deterministic)
// ============================================================
__global__ void finalize_kernel(float* __restrict__ out_scalars) {
    __shared__ double sh[8];
    int t = threadIdx.x;               // 256 threads

    double s = 0.0;
    for (int i = t; i < M_ROWS; i += 256) s += (double)g_rowloss[i];
    #pragma unroll
    for (int o = 16; o > 0; o >>= 1) s += __shfl_down_sync(0xffffffffu, s, o);
    if ((t & 31) == 0) sh[t >> 5] = s;
    __syncthreads();
    if (t == 0) {
        double tot = 0.0;
        #pragma unroll
        for (int i = 0; i < 8; i++) tot += sh[i];
        double mean = tot / (double)((size_t)M_ROWS * DIM);
        out_scalars[0] = (float)mean;   // commitment_loss
        out_scalars[1] = (float)mean;   // codebook_loss (numerically identical)
    }
    __syncthreads();

    double e = 0.0;
    for (int i = t; i < N_CODES; i += 256) {
        double p = (double)g_counts[i] * (1.0 / 16384.0);
        e -= p * log(p + 1e-10);
    }
    #pragma unroll
    for (int o = 16; o > 0; o >>= 1) e += __shfl_down_sync(0xffffffffu, e, o);
    if ((t & 31) == 0) sh[t >> 5] = e;
    __syncthreads();
    if (t == 0) {
        double tot = 0.0;
        #pragma unroll
        for (int i = 0; i < 8; i++) tot += sh[i];
        out_scalars[2] = (float)exp(tot);   // perplexity
    }
}

// ============================================================
extern "C" void kernel_launch(void* const* d_in, const int* in_sizes, int n_in,
                              void* d_out, int out_size) {
    const float* z_e = (const float*)d_in[0];   // [16,32,32,512] fp32
    const float* cb  = (const float*)d_in[1];   // [8192,512] fp32
    float* out = (float*)d_out;
    float* out_zq      = out;                                  // 8388608
    float* out_idx     = out + (size_t)M_ROWS * DIM;           // 16384
    float* out_scalars = out_idx + M_ROWS;                     // 3

    cnorm_kernel<<<N_CODES, 128>>>(cb);
    dist_argmin_kernel<<<M_ROWS / BM, 256>>>(z_e, cb, out_idx);
    gather_kernel<<<M_ROWS, 128>>>(z_e, cb, out_zq);
    finalize_kernel<<<1, 256>>>(out_scalars);
}

// round 9
// speedup vs baseline: 10.5188x; 10.5188x over previous
#include <cuda_runtime.h>
#include <cuda_bf16.h>
#include <stdint.h>
#include <math.h>

// ---------------- problem constants ----------------
#define M_ROWS   16384      // 16*32*32
#define N_CODES  8192
#define DIM      512
#define K_AUG    576        // 512 data + 1 (cnorm fold) + 63 zero pad
#define BKC      64         // bf16 per K chunk (128 bytes/row)
#define NCHUNK   9          // K_AUG / BKC
#define MT       128        // rows per CTA
#define NT       128        // codes per N-tile
#define NTILES   (N_CODES / NT)
#define GT       256        // GEMM threads (8 warps: 2 along M x 4 along N)

// ---------------- device scratch ----------------
__device__ __nv_bfloat16 g_Xb[(size_t)M_ROWS * K_AUG];   // [-2x, 1, 0...]
__device__ __nv_bfloat16 g_Cb[(size_t)N_CODES * K_AUG];  // [c, |c|^2, 0...]
__device__ int   g_cand[M_ROWS * 4];
__device__ float g_rowloss[M_ROWS];
__device__ int   g_counts[N_CODES];

// ---------------- SMEM layout (dynamic) ----------------
// [0, 147456)            : A resident, 9 chunks of 128x64 bf16 (xor swizzle)
// [147456, +67584)       : union { B 4-stage ring (4x16384) | D tile 128x132 f32 | merge }
#define SM_A      0
#define SM_U      147456
#define D_STRIDE  132
#define SM_TOTAL  (SM_U + MT * D_STRIDE * 4)   // 215040

// ---------------- PTX helpers (base sm_103 ISA only) ----------------
static __device__ __forceinline__ uint32_t smem_u32(const void* p){
    uint32_t a;
    asm("{ .reg .u64 t; cvta.to.shared.u64 t, %1; cvt.u32.u64 %0, t; }"
        : "=r"(a) : "l"(p));
    return a;
}
static __device__ __forceinline__ void cp16(uint32_t dst, const void* src){
    asm volatile("cp.async.cg.shared.global [%0], [%1], 16;"
                 :: "r"(dst), "l"(src) : "memory");
}
#define CP_COMMIT() asm volatile("cp.async.commit_group;" ::: "memory")
#define CP_WAIT2()  asm volatile("cp.async.wait_group 2;" ::: "memory")
#define CP_WAIT0()  asm volatile("cp.async.wait_group 0;" ::: "memory")

static __device__ __forceinline__ void ldmx4(uint32_t a, uint32_t& r0, uint32_t& r1,
                                             uint32_t& r2, uint32_t& r3){
    asm volatile("ldmatrix.sync.aligned.m8n8.x4.shared.b16 {%0,%1,%2,%3}, [%4];"
                 : "=r"(r0), "=r"(r1), "=r"(r2), "=r"(r3) : "r"(a));
}
static __device__ __forceinline__ void mma16816(float& c0, float& c1, float& c2, float& c3,
                                                uint32_t a0, uint32_t a1, uint32_t a2, uint32_t a3,
                                                uint32_t b0, uint32_t b1){
    asm volatile("mma.sync.aligned.m16n8k16.row.col.f32.bf16.bf16.f32 "
                 "{%0,%1,%2,%3}, {%4,%5,%6,%7}, {%8,%9}, {%0,%1,%2,%3};"
                 : "+f"(c0), "+f"(c1), "+f"(c2), "+f"(c3)
                 : "r"(a0), "r"(a1), "r"(a2), "r"(a3), "r"(b0), "r"(b1));
}

// ============================================================
// Conversion: Xb = bf16(-2 * z_e) augmented with [1, 0...]
// ============================================================
__global__ void conv_x_kernel(const float* __restrict__ X){
    int row = blockIdx.x, t = threadIdx.x;       // 16384 x 128
    float4 v = reinterpret_cast<const float4*>(X + (size_t)row * DIM)[t];
    __nv_bfloat16* dst = g_Xb + (size_t)row * K_AUG + t * 4;
    dst[0] = __float2bfloat16(-2.0f * v.x);
    dst[1] = __float2bfloat16(-2.0f * v.y);
    dst[2] = __float2bfloat16(-2.0f * v.z);
    dst[3] = __float2bfloat16(-2.0f * v.w);
    if (t < 64)
        g_Xb[(size_t)row * K_AUG + DIM + t] = __float2bfloat16(t == 0 ? 1.0f : 0.0f);
}

// ============================================================
// Conversion: Cb = bf16(c) augmented with [|c|^2, 0...]; zero histogram
// ============================================================
__global__ void conv_c_kernel(const float* __restrict__ C){
    int row = blockIdx.x, t = threadIdx.x;       // 8192 x 128
    float4 v = reinterpret_cast<const float4*>(C + (size_t)row * DIM)[t];
    __nv_bfloat16* dst = g_Cb + (size_t)row * K_AUG + t * 4;
    dst[0] = __float2bfloat16(v.x);
    dst[1] = __float2bfloat16(v.y);
    dst[2] = __float2bfloat16(v.z);
    dst[3] = __float2bfloat16(v.w);
    if (t >= 1 && t < 64)
        g_Cb[(size_t)row * K_AUG + DIM + t] = __float2bfloat16(0.0f);

    float s = v.x*v.x + v.y*v.y + v.z*v.z + v.w*v.w;
    #pragma unroll
    for (int o = 16; o > 0; o >>= 1) s += __shfl_down_sync(0xffffffffu, s, o);
    __shared__ float ws[4];
    if ((t & 31) == 0) ws[t >> 5] = s;
    __syncthreads();
    if (t == 0){
        g_Cb[(size_t)row * K_AUG + DIM] = __float2bfloat16(ws[0]+ws[1]+ws[2]+ws[3]);
        g_counts[row] = 0;
    }
}

// ============================================================
// Fused bf16 HMMA GEMM (scores = |c|^2 - 2 x.c) + per-row top-4
// ============================================================
__global__ __launch_bounds__(GT, 1) void gemm_topk_kernel(){
    extern __shared__ char smem[];
    const uint32_t sb = smem_u32(smem);
    const int tid = threadIdx.x;
    const int wid = tid >> 5, lane = tid & 31;
    const int row0 = blockIdx.x * MT;
    const int wm = (wid >> 2) * 64;      // warp M offset (0/64)
    const int wn = (wid & 3) * 32;       // warp N offset (0/32/64/96)

    // ---- load resident A: 9 chunks of 128x64 bf16, xor swizzle ----
    #pragma unroll
    for (int i = 0; i < 36; i++){
        int q = tid + i * GT;            // 0..9215 16B-units
        int kc = q >> 10;
        int qq = q & 1023;
        int cr = qq >> 3, c = qq & 7;
        uint32_t dst = sb + SM_A + kc * 16384 + cr * 128 + ((c ^ (cr & 7)) << 4);
        cp16(dst, g_Xb + (size_t)(row0 + cr) * K_AUG + kc * BKC + c * 8);
    }
    CP_COMMIT();
    CP_WAIT0();
    __syncthreads();

    // per-thread ldmatrix address components
    const int a_r16  = lane & 15;          // row within m16 tile
    const int a_cbit = lane >> 4;          // k 16B-chunk select
    const int b_roff = (lane & 7) + ((lane >> 4) << 3);
    const int b_cbit = (lane >> 3) & 1;

    // global running top-4 for this thread's (row, col-half)
    const int my_row  = tid >> 1;          // 0..127
    const int my_half = tid & 1;           // 0/1 (64 cols each)
    float m0 = 3.4e38f, m1 = 3.4e38f, m2 = 3.4e38f, m3 = 3.4e38f;
    int   j0 = 0, j1 = 0, j2 = 0, j3 = 0;

    for (int nt = 0; nt < NTILES; nt++){
        const int col0 = nt * NT;
        const __nv_bfloat16* Bt = g_Cb + (size_t)col0 * K_AUG;

        // B chunk loader: chunk KC into ring stage S (stage size 16 KB)
        auto load_b = [&](int KC, int S){
            if (KC < NCHUNK){
                #pragma unroll
                for (int i = 0; i < 4; i++){
                    int q = tid + i * GT;               // 0..1023 16B-units
                    int cr = q >> 3, c = q & 7;
                    uint32_t dst = sb + SM_U + S * 16384 + cr * 128
                                   + ((c ^ (cr & 7)) << 4);
                    cp16(dst, Bt + (size_t)cr * K_AUG + KC * BKC + c * 8);
                }
            }
            CP_COMMIT();
        };

        float acc[4][4][4];
        #pragma unroll
        for (int a = 0; a < 4; a++)
            #pragma unroll
            for (int b = 0; b < 4; b++)
                #pragma unroll
                for (int c = 0; c < 4; c++) acc[a][b][c] = 0.0f;

        load_b(0, 0);
        load_b(1, 1);

        for (int kc = 0; kc < NCHUNK; kc++){
            load_b(kc + 2, (kc + 2) & 3);
            CP_WAIT2();
            __syncthreads();

            const uint32_t abase = sb + SM_A + kc * 16384;
            const uint32_t bbase = sb + SM_U + (kc & 3) * 16384;
            #pragma unroll
            for (int ks = 0; ks < 4; ks++){
                uint32_t bf[8];
                #pragma unroll
                for (int g = 0; g < 2; g++){
                    int br = wn + g * 16 + b_roff;
                    int bc = ks * 2 + b_cbit;
                    ldmx4(bbase + br * 128 + ((bc ^ (br & 7)) << 4),
                          bf[g*4+0], bf[g*4+1], bf[g*4+2], bf[g*4+3]);
                }
                #pragma unroll
                for (int mf = 0; mf < 4; mf++){
                    int ar = wm + mf * 16 + a_r16;
                    int ac = ks * 2 + a_cbit;
                    uint32_t a0, a1, a2, a3;
                    ldmx4(abase + ar * 128 + ((ac ^ (ar & 7)) << 4), a0, a1, a2, a3);
                    mma16816(acc[mf][0][0], acc[mf][0][1], acc[mf][0][2], acc[mf][0][3],
                             a0, a1, a2, a3, bf[0], bf[1]);
                    mma16816(acc[mf][1][0], acc[mf][1][1], acc[mf][1][2], acc[mf][1][3],
                             a0, a1, a2, a3, bf[2], bf[3]);
                    mma16816(acc[mf][2][0], acc[mf][2][1], acc[mf][2][2], acc[mf][2][3],
                             a0, a1, a2, a3, bf[4], bf[5]);
                    mma16816(acc[mf][3][0], acc[mf][3][1], acc[mf][3][2], acc[mf][3][3],
                             a0, a1, a2, a3, bf[6], bf[7]);
                }
            }
        }
        CP_WAIT0();        // drain dangling cp.async groups before reusing union
        __syncthreads();   // all warps done with B stages; union becomes D tile

        // ---- spill accumulators to D smem (128 x 132 fp32) ----
        float* D = reinterpret_cast<float*>(smem + SM_U);
        {
            const int rb = wm + (lane >> 2);
            const int cb = wn + 2 * (lane & 3);
            #pragma unroll
            for (int mf = 0; mf < 4; mf++){
                #pragma unroll
                for (int nf = 0; nf < 4; nf++){
                    int r = rb + mf * 16, c = cb + nf * 8;
                    *reinterpret_cast<float2*>(&D[r * D_STRIDE + c]) =
                        make_float2(acc[mf][nf][0], acc[mf][nf][1]);
                    *reinterpret_cast<float2*>(&D[(r + 8) * D_STRIDE + c]) =
                        make_float2(acc[mf][nf][2], acc[mf][nf][3]);
                }
            }
        }
        __syncthreads();

        // ---- scan: 2 threads per row, 64 cols each, running global top-4 ----
        {
            const float* Drow = &D[my_row * D_STRIDE + my_half * 64];
            const int jbase = col0 + my_half * 64;
            #pragma unroll
            for (int q = 0; q < 16; q++){
                float4 v = reinterpret_cast<const float4*>(Drow)[q];
                #pragma unroll
                for (int e = 0; e < 4; e++){
                    float s = (e == 0) ? v.x : (e == 1) ? v.y : (e == 2) ? v.z : v.w;
                    int j = jbase + q * 4 + e;
                    if (s < m3){
                        if (s < m2){
                            m3 = m2; j3 = j2;
                            if (s < m1){
                                m2 = m1; j2 = j1;
                                if (s < m0){ m1 = m0; j1 = j0; m0 = s; j0 = j; }
                                else       { m1 = s; j1 = j; }
                            } else { m2 = s; j2 = j; }
                        } else { m3 = s; j3 = j; }
                    }
                }
            }
        }
        __syncthreads();   // scan reads done before next tile overwrites union
    }

    // ---- merge the two col-half top-4 lists per row -> global top-4 ----
    {
        float* V = reinterpret_cast<float*>(smem + SM_U);
        int*   J = reinterpret_cast<int*>(smem + SM_U + GT * 16);
        V[tid*4+0] = m0; V[tid*4+1] = m1; V[tid*4+2] = m2; V[tid*4+3] = m3;
        J[tid*4+0] = j0; J[tid*4+1] = j1; J[tid*4+2] = j2; J[tid*4+3] = j3;
        __syncthreads();
        if (my_half == 0){
            float cv[8]; int cj[8];
            #pragma unroll
            for (int i = 0; i < 4; i++){ cv[i] = V[tid*4+i]; cj[i] = J[tid*4+i]; }
            #pragma unroll
            for (int i = 0; i < 4; i++){ cv[4+i] = V[(tid+1)*4+i]; cj[4+i] = J[(tid+1)*4+i]; }
            #pragma unroll
            for (int s = 0; s < 4; s++){
                int best = s;
                #pragma unroll
                for (int i = s + 1; i < 8; i++)
                    if (cv[i] < cv[best] || (cv[i] == cv[best] && cj[i] < cj[best])) best = i;
                float tv = cv[s]; cv[s] = cv[best]; cv[best] = tv;
                int   tj = cj[s]; cj[s] = cj[best]; cj[best] = tj;
                g_cand[(row0 + my_row) * 4 + s] = cj[s];
            }
        }
    }
}

// ============================================================
// Exact fp32 rescore of 4 candidates + gather + per-row loss + histogram
// ============================================================
__global__ void rescore_gather_kernel(const float* __restrict__ X,
                                      const float* __restrict__ C,
                                      float* __restrict__ out_zq,
                                      float* __restrict__ out_idx){
    int row = blockIdx.x, t = threadIdx.x;      // 16384 x 128
    float4 x = reinterpret_cast<const float4*>(X + (size_t)row * DIM)[t];

    int cj[4]; float ps[4];
    #pragma unroll
    for (int i = 0; i < 4; i++){
        cj[i] = g_cand[row * 4 + i];
        float4 c = reinterpret_cast<const float4*>(C + (size_t)cj[i] * DIM)[t];
        float dx = c.x - x.x, dy = c.y - x.y, dz = c.z - x.z, dw = c.w - x.w;
        ps[i] = dx*dx + dy*dy + dz*dz + dw*dw;
    }
    #pragma unroll
    for (int o = 16; o > 0; o >>= 1){
        #pragma unroll
        for (int i = 0; i < 4; i++)
            ps[i] += __shfl_down_sync(0xffffffffu, ps[i], o);
    }
    __shared__ float rd[4][4];
    __shared__ int   sbj;
    if ((t & 31) == 0){
        #pragma unroll
        for (int i = 0; i < 4; i++) rd[t >> 5][i] = ps[i];
    }
    __syncthreads();
    if (t == 0){
        float d[4];
        #pragma unroll
        for (int i = 0; i < 4; i++) d[i] = rd[0][i] + rd[1][i] + rd[2][i] + rd[3][i];
        int bj = cj[0]; float bd = d[0];
        #pragma unroll
        for (int i = 1; i < 4; i++)
            if (d[i] < bd || (d[i] == bd && cj[i] < bj)){ bd = d[i]; bj = cj[i]; }
        sbj = bj;
        g_rowloss[row] = bd;
        atomicAdd(&g_counts[bj], 1);
        out_idx[row] = (float)bj;
    }
    __syncthreads();
    int bj = sbj;
    float4 c = reinterpret_cast<const float4*>(C + (size_t)bj * DIM)[t];
    float4 o;
    o.x = x.x + (c.x - x.x); o.y = x.y + (c.y - x.y);
    o.z = x.z + (c.z - x.z); o.w = x.w + (c.w - x.w);
    reinterpret_cast<float4*>(out_zq + (size_t)row * DIM)[t] = o;
}

// ============================================================
// Losses + perplexity (single block, deterministic)
// ============================================================
__global__ void finalize_kernel(float* __restrict__ out_scalars){
    int t = threadIdx.x;                      // 1024 threads
    __shared__ double shd[32];
    __shared__ float  shf[32];

    double s = 0.0;
    for (int i = t; i < M_ROWS; i += 1024) s += (double)g_rowloss[i];
    #pragma unroll
    for (int o = 16; o > 0; o >>= 1) s += __shfl_down_sync(0xffffffffu, s, o);
    if ((t & 31) == 0) shd[t >> 5] = s;
    __syncthreads();
    if (t == 0){
        double tot = 0.0;
        #pragma unroll
        for (int i = 0; i < 32; i++) tot += shd[i];
        float mean = (float)(tot / ((double)M_ROWS * (double)DIM));
        out_scalars[0] = mean;    // commitment_loss
        out_scalars[1] = mean;    // codebook_loss
    }
    __syncthreads();

    float e = 0.0f;
    for (int i = t; i < N_CODES; i += 1024){
        int c = g_counts[i];
        if (c){
            float p = (float)c * (1.0f / 16384.0f);
            e -= p * logf(p + 1e-10f);
        }
    }
    #pragma unroll
    for (int o = 16; o > 0; o >>= 1) e += __shfl_down_sync(0xffffffffu, e, o);
    if ((t & 31) == 0) shf[t >> 5] = e;
    __syncthreads();
    if (t == 0){
        float tot = 0.0f;
        #pragma unroll
        for (int i = 0; i < 32; i++) tot += shf[i];
        out_scalars[2] = expf(tot);   // perplexity
    }
}

// ============================================================
extern "C" void kernel_launch(void* const* d_in, const int* in_sizes, int n_in,
                              void* d_out, int out_size) {
    const float* z_e = (const float*)d_in[0];   // [16,32,32,512] fp32
    const float* cb  = (const float*)d_in[1];   // [8192,512] fp32
    float* out = (float*)d_out;
    float* out_zq      = out;                                  // 8388608
    float* out_idx     = out + (size_t)M_ROWS * DIM;           // 16384
    float* out_scalars = out_idx + M_ROWS;                     // 3

    cudaFuncSetAttribute(gemm_topk_kernel,
                         cudaFuncAttributeMaxDynamicSharedMemorySize, SM_TOTAL);

    conv_x_kernel<<<M_ROWS, 128>>>(z_e);
    conv_c_kernel<<<N_CODES, 128>>>(cb);
    gemm_topk_kernel<<<M_ROWS / MT, GT, SM_TOTAL>>>();
    rescore_gather_kernel<<<M_ROWS, 128>>>(z_e, cb, out_zq, out_idx);
    finalize_kernel<<<1, 1024>>>(out_scalars);
}